// round 1
// baseline (speedup 1.0000x reference)
#include <cuda_runtime.h>

#define NROWS 65536
#define DDIM 512
#define NUM_LABELS 512
#define NUM_DEMOG 4
#define NGROUP (NUM_LABELS * NUM_DEMOG)

// -------- scratch (device globals; no allocation allowed) --------
__device__ int    g_cnt[NGROUP];
__device__ int    g_off[NGROUP + 1];
__device__ int    g_cursor[NGROUP];
__device__ int    g_sorted[NROWS];
__device__ int    g_seg[NROWS];
__device__ double g_gm[NGROUP];
__device__ int    g_is64;

// -------- dtype detection: int64 labels have zero high words --------
__global__ void k_detect(const int* labels_raw) {
    if (threadIdx.x == 0) {
        int nz = 0;
        // First 64 int32 words = 256 bytes; safe under both int32 (256KB) and
        // int64 (512KB) layouts. If int64, every odd word is a high word == 0
        // (labels in [0,512)). If int32, odd words are random labels.
        for (int i = 1; i < 64; i += 2) nz += (labels_raw[i] != 0);
        g_is64 = (nz == 0) ? 1 : 0;
    }
}

__global__ void k_zero() {
    int i = blockIdx.x * blockDim.x + threadIdx.x;
    if (i < NGROUP) g_cnt[i] = 0;
}

__device__ __forceinline__ int load_idx_val(const void* p, int i, int is64) {
    if (is64) return (int)((const long long*)p)[i];
    return ((const int*)p)[i];
}

__global__ void k_hist(const void* labels, const void* demog) {
    int i = blockIdx.x * blockDim.x + threadIdx.x;
    if (i < NROWS) {
        int is64 = g_is64;
        int lab = load_idx_val(labels, i, is64);
        int dem = load_idx_val(demog, i, is64);
        int seg = dem * NUM_LABELS + lab;
        g_seg[i] = seg;
        atomicAdd(&g_cnt[seg], 1);
    }
}

// Single-CTA exclusive scan over 2048 counts (1024 threads, 2 elems each).
__global__ void k_scan() {
    __shared__ int s[1024];
    int t = threadIdx.x;
    int a = g_cnt[2 * t];
    int b = g_cnt[2 * t + 1];
    int pairsum = a + b;
    s[t] = pairsum;
    __syncthreads();
    for (int d = 1; d < 1024; d <<= 1) {
        int v = (t >= d) ? s[t - d] : 0;
        __syncthreads();
        s[t] += v;
        __syncthreads();
    }
    int incl = s[t];
    int excl = incl - pairsum;
    g_off[2 * t]     = excl;
    g_off[2 * t + 1] = excl + a;
    g_cursor[2 * t]     = excl;
    g_cursor[2 * t + 1] = excl + a;
    if (t == 1023) g_off[2048] = incl;
}

__global__ void k_scatter() {
    int i = blockIdx.x * blockDim.x + threadIdx.x;
    if (i < NROWS) {
        int seg = g_seg[i];
        int pos = atomicAdd(&g_cursor[seg], 1);
        g_sorted[pos] = i;
    }
}

// One CTA per group: gather rows, accumulate column sums (regs) + sum of squares.
// grp_mean_dist = (sum||x||^2 - ||sum x||^2/cnt) / cnt.
__global__ void __launch_bounds__(128) k_group(const float4* __restrict__ feats) {
    int g = blockIdx.x;
    int t = threadIdx.x;  // 128 threads, thread t owns columns [4t, 4t+4)
    int start = g_off[g];
    int end   = g_off[g + 1];

    __shared__ int    sidx[128];
    __shared__ double red[128];

    float4 acc = make_float4(0.f, 0.f, 0.f, 0.f);
    float  ssq = 0.f;

    for (int base = start; base < end; base += 128) {
        int n = min(128, end - base);
        __syncthreads();
        if (t < n) sidx[t] = g_sorted[base + t];
        __syncthreads();

        int r = 0;
        for (; r + 4 <= n; r += 4) {
            float4 v0 = feats[(size_t)sidx[r + 0] * 128 + t];
            float4 v1 = feats[(size_t)sidx[r + 1] * 128 + t];
            float4 v2 = feats[(size_t)sidx[r + 2] * 128 + t];
            float4 v3 = feats[(size_t)sidx[r + 3] * 128 + t];
            acc.x += v0.x; acc.y += v0.y; acc.z += v0.z; acc.w += v0.w;
            ssq += v0.x * v0.x + v0.y * v0.y + v0.z * v0.z + v0.w * v0.w;
            acc.x += v1.x; acc.y += v1.y; acc.z += v1.z; acc.w += v1.w;
            ssq += v1.x * v1.x + v1.y * v1.y + v1.z * v1.z + v1.w * v1.w;
            acc.x += v2.x; acc.y += v2.y; acc.z += v2.z; acc.w += v2.w;
            ssq += v2.x * v2.x + v2.y * v2.y + v2.z * v2.z + v2.w * v2.w;
            acc.x += v3.x; acc.y += v3.y; acc.z += v3.z; acc.w += v3.w;
            ssq += v3.x * v3.x + v3.y * v3.y + v3.z * v3.z + v3.w * v3.w;
        }
        for (; r < n; ++r) {
            float4 v = feats[(size_t)sidx[r] * 128 + t];
            acc.x += v.x; acc.y += v.y; acc.z += v.z; acc.w += v.w;
            ssq += v.x * v.x + v.y * v.y + v.z * v.z + v.w * v.w;
        }
    }

    // ||sum||^2 contribution from this thread's 4 unique columns
    double nrm = (double)acc.x * acc.x + (double)acc.y * acc.y +
                 (double)acc.z * acc.z + (double)acc.w * acc.w;

    __syncthreads();
    red[t] = (double)ssq;
    __syncthreads();
    for (int s = 64; s > 0; s >>= 1) {
        if (t < s) red[t] += red[t + s];
        __syncthreads();
    }
    double sumsq = red[0];
    __syncthreads();
    red[t] = nrm;
    __syncthreads();
    for (int s = 64; s > 0; s >>= 1) {
        if (t < s) red[t] += red[t + s];
        __syncthreads();
    }
    if (t == 0) {
        double normsq = red[0];
        int cnt = end - start;
        double denom = (cnt > 0) ? (double)cnt : 1.0;
        g_gm[g] = (sumsq - normsq / denom) / denom;
    }
}

// Single-CTA finalize: intra[d] = mean over present groups; loss = MAD of intra.
__global__ void k_final(float* out) {
    int t = threadIdx.x;  // 512 threads, one label each
    __shared__ double ssum[512];
    __shared__ int    scnt[512];
    __shared__ double s_intra[NUM_DEMOG];

    for (int d = 0; d < NUM_DEMOG; ++d) {
        int g = d * NUM_LABELS + t;
        int c = g_off[g + 1] - g_off[g];
        ssum[t] = (c > 0) ? g_gm[g] : 0.0;
        scnt[t] = (c > 0) ? 1 : 0;
        __syncthreads();
        for (int s = 256; s > 0; s >>= 1) {
            if (t < s) { ssum[t] += ssum[t + s]; scnt[t] += scnt[t + s]; }
            __syncthreads();
        }
        if (t == 0) {
            int np = scnt[0] > 0 ? scnt[0] : 1;
            s_intra[d] = ssum[0] / (double)np;
        }
        __syncthreads();
    }
    if (t == 0) {
        double mu = 0.0;
        for (int d = 0; d < NUM_DEMOG; ++d) mu += s_intra[d];
        mu /= (double)NUM_DEMOG;
        double loss = 0.0;
        for (int d = 0; d < NUM_DEMOG; ++d) loss += fabs(s_intra[d] - mu);
        loss /= (double)NUM_DEMOG;
        out[0] = (float)loss;
    }
}

extern "C" void kernel_launch(void* const* d_in, const int* in_sizes, int n_in,
                              void* d_out, int out_size) {
    const float* feats  = (const float*)d_in[0];
    const void*  labels = d_in[1];
    const void*  demog  = d_in[2];
    float* out = (float*)d_out;

    k_detect<<<1, 32>>>((const int*)labels);
    k_zero<<<(NGROUP + 255) / 256, 256>>>();
    k_hist<<<(NROWS + 255) / 256, 256>>>(labels, demog);
    k_scan<<<1, 1024>>>();
    k_scatter<<<(NROWS + 255) / 256, 256>>>();
    k_group<<<NGROUP, 128>>>((const float4*)feats);
    k_final<<<1, 512>>>(out);
}